// round 8
// baseline (speedup 1.0000x reference)
#include <cuda_runtime.h>
#include <cuda_bf16.h>
#include <cstdint>
#include <cstring>

#define NN 50000
#define EE 800000
#define FD 256          // H*HID
#define NEG 0.2f
#define NB 49           // ceil(NN/1024)

__device__ __forceinline__ uint32_t bf2_as_u32(__nv_bfloat162 v) {
    uint32_t u;
    memcpy(&u, &v, 4);
    return u;
}

// ---------------- scratch (device globals; no allocation allowed) ------------
__device__ __nv_bfloat16 g_featb[(size_t)NN * FD];   // bf16 post-GEMM features
__device__ float g_hA[(size_t)NN * FD];
__device__ float g_hB[(size_t)NN * FD];
__device__ float g_el[NN * 4];
__device__ float g_er[NN * 4];
__device__ float g_f4[NN * 8];
__device__ float g_r4[NN * 8];
__device__ int   g_cnt[NN];
__device__ int   g_rowptr[NN + 1];
__device__ int   g_cur[NN];
__device__ int   g_csrc[EE];
__device__ int   g_bsum[64];

// ---------------- CSR build --------------------------------------------------
__global__ void k_zero_cnt(int* cnt) {
    int i = blockIdx.x * blockDim.x + threadIdx.x;
    if (i < NN) cnt[i] = 0;
}

__global__ void k_histo(const int* __restrict__ dst, int* __restrict__ cnt, int E) {
    for (int i = blockIdx.x * blockDim.x + threadIdx.x; i < E; i += gridDim.x * blockDim.x)
        atomicAdd(&cnt[dst[i]], 1);
}

__global__ void k_scan_part(const int* __restrict__ cnt) {
    __shared__ int sh[1024];
    int i = blockIdx.x * 1024 + threadIdx.x;
    sh[threadIdx.x] = (i < NN) ? cnt[i] : 0;
    __syncthreads();
    for (int o = 512; o > 0; o >>= 1) {
        if (threadIdx.x < o) sh[threadIdx.x] += sh[threadIdx.x + o];
        __syncthreads();
    }
    if (threadIdx.x == 0) g_bsum[blockIdx.x] = sh[0];
}

__global__ void k_scan_small(int* rowptr) {
    __shared__ int sh[64];
    int t = threadIdx.x;
    int v = (t < NB) ? g_bsum[t] : 0;
    sh[t] = v;
    __syncthreads();
    #pragma unroll
    for (int o = 1; o < 64; o <<= 1) {
        int u = (t >= o) ? sh[t - o] : 0;
        __syncthreads();
        sh[t] += u;
        __syncthreads();
    }
    if (t < NB) g_bsum[t] = sh[t] - v;       // exclusive prefix
    if (t == 63) rowptr[NN] = sh[63];
}

__global__ void k_scan_final(const int* __restrict__ cnt, int* __restrict__ rowptr,
                             int* __restrict__ cur) {
    __shared__ int sh[1024];
    int tid = threadIdx.x;
    int i = blockIdx.x * 1024 + tid;
    int v = (i < NN) ? cnt[i] : 0;
    sh[tid] = v;
    __syncthreads();
    #pragma unroll
    for (int o = 1; o < 1024; o <<= 1) {
        int t = (tid >= o) ? sh[tid - o] : 0;
        __syncthreads();
        sh[tid] += t;
        __syncthreads();
    }
    if (i < NN) { int ex = g_bsum[blockIdx.x] + sh[tid] - v; rowptr[i] = ex; cur[i] = ex; }
}

__global__ void k_scatter(const int* __restrict__ src, const int* __restrict__ dst,
                          int* __restrict__ cur, int* __restrict__ csrc, int E) {
    for (int i = blockIdx.x * blockDim.x + threadIdx.x; i < E; i += gridDim.x * blockDim.x) {
        int d = dst[i];
        int p = atomicAdd(&cur[d], 1);
        csrc[p] = src[i];
    }
}

// ---------------- tf32 GEMM BN=128 (cp.async dbuf) + fused el/er -------------
// C[M,256] = A[M,K] @ B[256,K]^T, fp32 in (tf32 mma), bf16 out, fp32 accum.
// blockIdx.x covers 128 cols = 2 heads; warp wn (0/1) owns exactly one head.
#define BM 128
#define BN 128
#define BK 32
#define BKP 36                       // +4 pad: bank = (4r+c)%32, bijective
#define ASZ (BM * BKP)
#define BSZ (BN * BKP)
#define GEMM_SMEM ((2 * (ASZ + BSZ)) * (int)sizeof(float))   // 73728 B

__device__ __forceinline__ void cp16(uint32_t s, const void* g) {
    asm volatile("cp.async.cg.shared.global [%0], [%1], 16;" :: "r"(s), "l"(g));
}

__device__ __forceinline__ void mma_tf32(float (&d)[4], const uint32_t (&a)[4],
                                         const uint32_t (&b)[2]) {
    asm volatile(
        "mma.sync.aligned.m16n8k8.row.col.f32.tf32.tf32.f32 "
        "{%0,%1,%2,%3},{%4,%5,%6,%7},{%8,%9},{%0,%1,%2,%3};"
        : "+f"(d[0]), "+f"(d[1]), "+f"(d[2]), "+f"(d[3])
        : "r"(a[0]), "r"(a[1]), "r"(a[2]), "r"(a[3]), "r"(b[0]), "r"(b[1]));
}

__global__ void __launch_bounds__(256) k_gemm_tf32(
        const float* __restrict__ A, const float* __restrict__ B,
        __nv_bfloat16* __restrict__ C,
        const float* __restrict__ al, const float* __restrict__ ar,
        float* __restrict__ el, float* __restrict__ er, int M, int K) {
    extern __shared__ float smem[];
    float* Asm = smem;                 // [2][BM][BKP]
    float* Bsm = smem + 2 * ASZ;       // [2][BN][BKP]
    __shared__ float sAl[BN], sAr[BN];

    const int bx = blockIdx.x;
    const int bm = blockIdx.y * BM, bn = bx * BN;
    const int tid = threadIdx.x;
    const int warp = tid >> 5, lane = tid & 31;
    const int wm = warp & 3, wn = warp >> 2;      // wn in {0,1} = head within block
    const int r = lane >> 2, c = lane & 3;
    const int hg = bx * 2 + wn;                   // global head for this warp

    if (tid < BN) { sAl[tid] = al[bn + tid]; sAr[tid] = ar[bn + tid]; }

    // loaders: row = tid>>1 (0..127), half = 16 floats; A and B tiles same shape
    const int lrow = tid >> 1, lcol = (tid & 1) * 16;
    const bool aok = (bm + lrow) < M;

    float acc[2][8][4];
    #pragma unroll
    for (int mt = 0; mt < 2; mt++)
        #pragma unroll
        for (int nt = 0; nt < 8; nt++)
            #pragma unroll
            for (int i = 0; i < 4; i++) acc[mt][nt][i] = 0.f;

    const int ntile = K / BK;

    auto issue = [&](int buf, int kt) {
        if (aok) {
            uint32_t sa = (uint32_t)__cvta_generic_to_shared(
                &Asm[(buf * BM + lrow) * BKP + lcol]);
            const float* ga = &A[(size_t)(bm + lrow) * K + kt + lcol];
            #pragma unroll
            for (int j = 0; j < 4; j++) cp16(sa + j * 16, ga + j * 4);
        }
        uint32_t sb = (uint32_t)__cvta_generic_to_shared(
            &Bsm[(buf * BN + lrow) * BKP + lcol]);
        const float* gb = &B[(size_t)(bn + lrow) * K + kt + lcol];
        #pragma unroll
        for (int j = 0; j < 4; j++) cp16(sb + j * 16, gb + j * 4);
    };

    issue(0, 0);
    asm volatile("cp.async.commit_group;");

    for (int t = 0; t < ntile; t++) {
        if (t + 1 < ntile) {
            issue((t + 1) & 1, (t + 1) * BK);
            asm volatile("cp.async.commit_group;");
            asm volatile("cp.async.wait_group 1;");
        } else {
            asm volatile("cp.async.wait_group 0;");
        }
        __syncthreads();
        const float* Ab = &Asm[((t & 1) * BM) * BKP];
        const float* Bb = &Bsm[((t & 1) * BN) * BKP];
        #pragma unroll
        for (int kk = 0; kk < BK; kk += 8) {
            uint32_t af[2][4], bf[8][2];
            #pragma unroll
            for (int mt = 0; mt < 2; mt++) {
                int row0 = wm * 32 + mt * 16 + r;
                af[mt][0] = __float_as_uint(Ab[row0 * BKP + kk + c]);
                af[mt][1] = __float_as_uint(Ab[(row0 + 8) * BKP + kk + c]);
                af[mt][2] = __float_as_uint(Ab[row0 * BKP + kk + c + 4]);
                af[mt][3] = __float_as_uint(Ab[(row0 + 8) * BKP + kk + c + 4]);
            }
            #pragma unroll
            for (int nt = 0; nt < 8; nt++) {
                int col0 = wn * 64 + nt * 8 + r;
                bf[nt][0] = __float_as_uint(Bb[col0 * BKP + kk + c]);
                bf[nt][1] = __float_as_uint(Bb[col0 * BKP + kk + c + 4]);
            }
            #pragma unroll
            for (int mt = 0; mt < 2; mt++)
                #pragma unroll
                for (int nt = 0; nt < 8; nt++)
                    mma_tf32(acc[mt][nt], af[mt], bf[nt]);
        }
        __syncthreads();
    }

    // ---- store bf16 feat ----
    #pragma unroll
    for (int mt = 0; mt < 2; mt++) {
        #pragma unroll
        for (int nt = 0; nt < 8; nt++) {
            int row = bm + wm * 32 + mt * 16 + r;
            int col = bn + wn * 64 + nt * 8 + 2 * c;
            if (row < M)
                *(__nv_bfloat162*)&C[(size_t)row * FD + col] =
                    __floats2bfloat162_rn(acc[mt][nt][0], acc[mt][nt][1]);
            if (row + 8 < M)
                *(__nv_bfloat162*)&C[(size_t)(row + 8) * FD + col] =
                    __floats2bfloat162_rn(acc[mt][nt][2], acc[mt][nt][3]);
        }
    }

    // ---- fused el/er: this warp owns (rows wm*32..+31, head hg) ----
    #pragma unroll
    for (int mt = 0; mt < 2; mt++) {
        #pragma unroll
        for (int rh = 0; rh < 2; rh++) {
            float se = 0.f, sr2 = 0.f;
            #pragma unroll
            for (int nt = 0; nt < 8; nt++) {
                int col = wn * 64 + nt * 8 + 2 * c;
                float a0 = acc[mt][nt][rh * 2], a1 = acc[mt][nt][rh * 2 + 1];
                se  += a0 * sAl[col] + a1 * sAl[col + 1];
                sr2 += a0 * sAr[col] + a1 * sAr[col + 1];
            }
            se  += __shfl_xor_sync(0xffffffffu, se, 1);
            se  += __shfl_xor_sync(0xffffffffu, se, 2);
            sr2 += __shfl_xor_sync(0xffffffffu, sr2, 1);
            sr2 += __shfl_xor_sync(0xffffffffu, sr2, 2);
            if (c == 0) {
                int row = bm + wm * 32 + mt * 16 + rh * 8 + r;
                if (row < M) {
                    el[row * 4 + hg] = se;
                    er[row * 4 + hg] = sr2;
                }
            }
        }
    }
}

// ---------------- fused edge aggregation: warp per node, bf16 gather ---------
__global__ void __launch_bounds__(128) k_edge_agg(
        const uint4* __restrict__ featb,      // [N][32] x (8 bf16)
        const float4* __restrict__ el4, const float4* __restrict__ er4,
        const int* __restrict__ rowptr, const int* __restrict__ csrc,
        const float4* __restrict__ hprev4, const float4* __restrict__ bias4,
        float4* __restrict__ hout4) {
    int w = threadIdx.x >> 5;
    int n = blockIdx.x * 4 + w;
    int lane = threadIdx.x & 31;
    if (n >= NN) return;
    int head = lane >> 3;
    __shared__ int   ssrc[4][32];
    __shared__ float sw[4][32][4];
    int beg = rowptr[n], end = rowptr[n + 1];
    float4 erd = er4[n];
    float acc[8];
    #pragma unroll
    for (int i = 0; i < 8; i++) acc[i] = 0.f;
    float4 dl = make_float4(0.f, 0.f, 0.f, 0.f);

    #define ACCUM(fv, wgt) do {                                             \
        const __nv_bfloat162* _p = (const __nv_bfloat162*)&(fv);            \
        _Pragma("unroll")                                                   \
        for (int _j = 0; _j < 4; _j++) {                                    \
            float2 _v = __bfloat1622float2(_p[_j]);                         \
            acc[2 * _j]     = fmaf(_v.x, (wgt), acc[2 * _j]);               \
            acc[2 * _j + 1] = fmaf(_v.y, (wgt), acc[2 * _j + 1]);           \
        } } while (0)

    for (int base = beg; base < end; base += 32) {
        int cnt = min(32, end - base);
        if (lane < cnt) {
            int s = csrc[base + lane];
            ssrc[w][lane] = s;
            float4 le = el4[s];
            float x0 = le.x + erd.x; x0 = x0 > 0.f ? x0 : NEG * x0;
            float x1 = le.y + erd.y; x1 = x1 > 0.f ? x1 : NEG * x1;
            float x2 = le.z + erd.z; x2 = x2 > 0.f ? x2 : NEG * x2;
            float x3 = le.w + erd.w; x3 = x3 > 0.f ? x3 : NEG * x3;
            float w0 = expf(x0), w1 = expf(x1), w2 = expf(x2), w3 = expf(x3);
            sw[w][lane][0] = w0; sw[w][lane][1] = w1;
            sw[w][lane][2] = w2; sw[w][lane][3] = w3;
            dl.x += w0; dl.y += w1; dl.z += w2; dl.w += w3;
        }
        __syncwarp();
        int e = 0;
        for (; e + 4 <= cnt; e += 4) {
            uint4 f0 = featb[(size_t)ssrc[w][e]     * 32 + lane];
            uint4 f1 = featb[(size_t)ssrc[w][e + 1] * 32 + lane];
            uint4 f2 = featb[(size_t)ssrc[w][e + 2] * 32 + lane];
            uint4 f3 = featb[(size_t)ssrc[w][e + 3] * 32 + lane];
            float w0 = sw[w][e][head],     w1 = sw[w][e + 1][head];
            float w2 = sw[w][e + 2][head], w3 = sw[w][e + 3][head];
            ACCUM(f0, w0); ACCUM(f1, w1); ACCUM(f2, w2); ACCUM(f3, w3);
        }
        for (; e < cnt; e++) {
            uint4 fv = featb[(size_t)ssrc[w][e] * 32 + lane];
            float wg = sw[w][e][head];
            ACCUM(fv, wg);
        }
        __syncwarp();
    }
    #undef ACCUM

    #pragma unroll
    for (int o = 16; o > 0; o >>= 1) {
        dl.x += __shfl_xor_sync(0xffffffffu, dl.x, o);
        dl.y += __shfl_xor_sync(0xffffffffu, dl.y, o);
        dl.z += __shfl_xor_sync(0xffffffffu, dl.z, o);
        dl.w += __shfl_xor_sync(0xffffffffu, dl.w, o);
    }
    float den = (head == 0) ? dl.x : (head == 1) ? dl.y : (head == 2) ? dl.z : dl.w;
    float inv = (end > beg) ? 1.f / den : 0.f;
    float4 b0 = bias4[lane * 2], b1 = bias4[lane * 2 + 1];
    float4 v0 = make_float4(acc[0] * inv + b0.x, acc[1] * inv + b0.y,
                            acc[2] * inv + b0.z, acc[3] * inv + b0.w);
    float4 v1 = make_float4(acc[4] * inv + b1.x, acc[5] * inv + b1.y,
                            acc[6] * inv + b1.z, acc[7] * inv + b1.w);
    if (hprev4) {
        float4 p0 = hprev4[(size_t)n * 64 + lane * 2];
        float4 p1 = hprev4[(size_t)n * 64 + lane * 2 + 1];
        v0.x += p0.x; v0.y += p0.y; v0.z += p0.z; v0.w += p0.w;
        v1.x += p1.x; v1.y += p1.y; v1.z += p1.z; v1.w += p1.w;
    }
    v0.x = v0.x > 0.f ? v0.x : expm1f(v0.x);
    v0.y = v0.y > 0.f ? v0.y : expm1f(v0.y);
    v0.z = v0.z > 0.f ? v0.z : expm1f(v0.z);
    v0.w = v0.w > 0.f ? v0.w : expm1f(v0.w);
    v1.x = v1.x > 0.f ? v1.x : expm1f(v1.x);
    v1.y = v1.y > 0.f ? v1.y : expm1f(v1.y);
    v1.z = v1.z > 0.f ? v1.z : expm1f(v1.z);
    v1.w = v1.w > 0.f ? v1.w : expm1f(v1.w);
    hout4[(size_t)n * 64 + lane * 2]     = v0;
    hout4[(size_t)n * 64 + lane * 2 + 1] = v1;
}

// ---------------- layer-4 projection + el/er (merged) ------------------------
__global__ void k_l4_proj(const float* __restrict__ h, const float* __restrict__ W4,
                          const float* __restrict__ rW4,
                          const float* __restrict__ al4, const float* __restrict__ ar4,
                          float* __restrict__ f4, float* __restrict__ r4,
                          float* __restrict__ el, float* __restrict__ er) {
    int n = blockIdx.x * 8 + (threadIdx.x >> 5);
    int lane = threadIdx.x & 31;
    if (n >= NN) return;
    float acc[16];
    #pragma unroll
    for (int o = 0; o < 16; o++) acc[o] = 0.f;
    const float* hr = h + (size_t)n * FD;
    for (int k = lane; k < FD; k += 32) {
        float hv = hr[k];
        #pragma unroll
        for (int o = 0; o < 8; o++) acc[o]     = fmaf(hv, W4[o * FD + k], acc[o]);
        #pragma unroll
        for (int o = 0; o < 8; o++) acc[8 + o] = fmaf(hv, rW4[o * FD + k], acc[8 + o]);
    }
    #pragma unroll
    for (int o = 0; o < 16; o++)
        #pragma unroll
        for (int off = 16; off > 0; off >>= 1)
            acc[o] += __shfl_xor_sync(0xffffffffu, acc[o], off);
    if (lane < 8) {
        f4[n * 8 + lane] = acc[lane];
        r4[n * 8 + lane] = acc[8 + lane];
    }
    if (lane < 4) {
        el[n * 4 + lane] = acc[2 * lane] * al4[2 * lane] +
                           acc[2 * lane + 1] * al4[2 * lane + 1];
        er[n * 4 + lane] = acc[2 * lane] * ar4[2 * lane] +
                           acc[2 * lane + 1] * ar4[2 * lane + 1];
    }
}

// ---------------- layer-4 edge agg + softmax + head-mean ---------------------
__global__ void k_l4_edge(const float* __restrict__ f4, const float* __restrict__ el,
                          const float* __restrict__ er, const int* __restrict__ rowptr,
                          const int* __restrict__ csrc, const float* __restrict__ r4,
                          const float* __restrict__ b4, float* __restrict__ out) {
    int n = blockIdx.x * 8 + (threadIdx.x >> 5);
    int lane = threadIdx.x & 31;
    if (n >= NN) return;
    int beg = rowptr[n], end = rowptr[n + 1];
    float4 erd = ((const float4*)er)[n];
    float acc[8] = {0, 0, 0, 0, 0, 0, 0, 0};
    float den[4] = {0, 0, 0, 0};
    for (int e = beg + lane; e < end; e += 32) {
        int s = csrc[e];
        float4 le = ((const float4*)el)[s];
        float x0 = le.x + erd.x; x0 = x0 > 0.f ? x0 : NEG * x0;
        float x1 = le.y + erd.y; x1 = x1 > 0.f ? x1 : NEG * x1;
        float x2 = le.z + erd.z; x2 = x2 > 0.f ? x2 : NEG * x2;
        float x3 = le.w + erd.w; x3 = x3 > 0.f ? x3 : NEG * x3;
        float w0 = expf(x0), w1 = expf(x1), w2 = expf(x2), w3 = expf(x3);
        den[0] += w0; den[1] += w1; den[2] += w2; den[3] += w3;
        float4 f0 = ((const float4*)f4)[s * 2];
        float4 f1 = ((const float4*)f4)[s * 2 + 1];
        acc[0] = fmaf(f0.x, w0, acc[0]);  acc[1] = fmaf(f0.y, w0, acc[1]);
        acc[2] = fmaf(f0.z, w1, acc[2]);  acc[3] = fmaf(f0.w, w1, acc[3]);
        acc[4] = fmaf(f1.x, w2, acc[4]);  acc[5] = fmaf(f1.y, w2, acc[5]);
        acc[6] = fmaf(f1.z, w3, acc[6]);  acc[7] = fmaf(f1.w, w3, acc[7]);
    }
    #pragma unroll
    for (int off = 16; off > 0; off >>= 1) {
        #pragma unroll
        for (int o = 0; o < 8; o++) acc[o] += __shfl_xor_sync(0xffffffffu, acc[o], off);
        #pragma unroll
        for (int h = 0; h < 4; h++) den[h] += __shfl_xor_sync(0xffffffffu, den[h], off);
    }
    if (lane == 0) {
        bool has = end > beg;
        float o0 = 0.f, o1 = 0.f;
        #pragma unroll
        for (int h = 0; h < 4; h++) {
            float r0 = has ? acc[2 * h] / den[h] : 0.f;
            float r1 = has ? acc[2 * h + 1] / den[h] : 0.f;
            r0 += r4[n * 8 + 2 * h] + b4[2 * h];
            r1 += r4[n * 8 + 2 * h + 1] + b4[2 * h + 1];
            float m = fmaxf(r0, r1);
            float e0 = expf(r0 - m), e1 = expf(r1 - m);
            float s = e0 + e1;
            o0 += e0 / s;
            o1 += e1 / s;
        }
        out[n * 2 + 0] = o0 * 0.25f;
        out[n * 2 + 1] = o1 * 0.25f;
    }
}

// ---------------- host launcher ----------------------------------------------
extern "C" void kernel_launch(void* const* d_in, const int* in_sizes, int n_in,
                              void* d_out, int out_size) {
    const float* x     = (const float*)d_in[0];
    const int*   src   = (const int*)  d_in[1];
    const int*   dst   = (const int*)  d_in[2];
    const float* W1    = (const float*)d_in[3];
    const float* al1   = (const float*)d_in[4];
    const float* ar1   = (const float*)d_in[5];
    const float* b1    = (const float*)d_in[6];
    const float* W2    = (const float*)d_in[7];
    const float* al2   = (const float*)d_in[8];
    const float* ar2   = (const float*)d_in[9];
    const float* b2    = (const float*)d_in[10];
    const float* W3    = (const float*)d_in[11];
    const float* al3   = (const float*)d_in[12];
    const float* ar3   = (const float*)d_in[13];
    const float* b3    = (const float*)d_in[14];
    const float* W4    = (const float*)d_in[15];
    const float* al4   = (const float*)d_in[16];
    const float* ar4   = (const float*)d_in[17];
    const float* b4    = (const float*)d_in[18];
    const float* resW4 = (const float*)d_in[19];
    float* out = (float*)d_out;
    const int E = in_sizes[1];

    __nv_bfloat16* featb;
    float *hA, *hB, *el, *er, *f4, *r4;
    int *cnt, *rowptr, *cur, *csrc;
    cudaGetSymbolAddress((void**)&featb,  g_featb);
    cudaGetSymbolAddress((void**)&hA,     g_hA);
    cudaGetSymbolAddress((void**)&hB,     g_hB);
    cudaGetSymbolAddress((void**)&el,     g_el);
    cudaGetSymbolAddress((void**)&er,     g_er);
    cudaGetSymbolAddress((void**)&f4,     g_f4);
    cudaGetSymbolAddress((void**)&r4,     g_r4);
    cudaGetSymbolAddress((void**)&cnt,    g_cnt);
    cudaGetSymbolAddress((void**)&rowptr, g_rowptr);
    cudaGetSymbolAddress((void**)&cur,    g_cur);
    cudaGetSymbolAddress((void**)&csrc,   g_csrc);

    cudaFuncSetAttribute(k_gemm_tf32,
                         cudaFuncAttributeMaxDynamicSharedMemorySize, GEMM_SMEM);

    // ---- CSR by dst ----
    k_zero_cnt<<<(NN + 255) / 256, 256>>>(cnt);
    k_histo<<<1024, 256>>>(dst, cnt, E);
    k_scan_part<<<NB, 1024>>>(cnt);
    k_scan_small<<<1, 64>>>(rowptr);
    k_scan_final<<<NB, 1024>>>(cnt, rowptr, cur);
    k_scatter<<<1024, 256>>>(src, dst, cur, csrc, E);

    dim3 gemm_grid(FD / BN, (NN + BM - 1) / BM);   // (2, 391)
    const int agg_grid = (NN + 3) / 4;

    // ---- layer 1 ----
    k_gemm_tf32<<<gemm_grid, 256, GEMM_SMEM>>>(x, W1, featb, al1, ar1, el, er, NN, 128);
    k_edge_agg<<<agg_grid, 128>>>((const uint4*)featb, (const float4*)el,
                                  (const float4*)er, rowptr, csrc, nullptr,
                                  (const float4*)b1, (float4*)hA);

    // ---- layer 2 ----
    k_gemm_tf32<<<gemm_grid, 256, GEMM_SMEM>>>(hA, W2, featb, al2, ar2, el, er, NN, FD);
    k_edge_agg<<<agg_grid, 128>>>((const uint4*)featb, (const float4*)el,
                                  (const float4*)er, rowptr, csrc,
                                  (const float4*)hA, (const float4*)b2, (float4*)hB);

    // ---- layer 3 ----
    k_gemm_tf32<<<gemm_grid, 256, GEMM_SMEM>>>(hB, W3, featb, al3, ar3, el, er, NN, FD);
    k_edge_agg<<<agg_grid, 128>>>((const uint4*)featb, (const float4*)el,
                                  (const float4*)er, rowptr, csrc,
                                  (const float4*)hB, (const float4*)b3, (float4*)hA);

    // ---- layer 4 ----
    k_l4_proj<<<(NN + 7) / 8, 256>>>(hA, W4, resW4, al4, ar4, f4, r4, el, er);
    k_l4_edge<<<(NN + 7) / 8, 256>>>(f4, el, er, rowptr, csrc, r4, b4, out);
}

// round 9
// speedup vs baseline: 1.2019x; 1.2019x over previous
#include <cuda_runtime.h>
#include <cuda_fp16.h>
#include <cstdint>
#include <cstring>

#define NN 50000
#define EE 800000
#define FD 256          // H*HID
#define NEG 0.2f
#define NB 49           // ceil(NN/1024)

__device__ __forceinline__ uint32_t h2_as_u32(__half2 v) {
    uint32_t u;
    memcpy(&u, &v, 4);
    return u;
}

// ---------------- scratch (device globals; no allocation allowed) ------------
__device__ __half g_feath[(size_t)NN * FD];   // fp16 post-GEMM features
__device__ __half g_xh[(size_t)NN * 128];     // fp16 input x
__device__ __half g_hinh[(size_t)NN * FD];    // fp16 GEMM input (layers 2,3)
__device__ __half g_W1h[256 * 128];
__device__ __half g_W2h[256 * 256];
__device__ __half g_W3h[256 * 256];
__device__ float g_hA[(size_t)NN * FD];
__device__ float g_hB[(size_t)NN * FD];
__device__ float g_el[NN * 4];
__device__ float g_er[NN * 4];
__device__ float g_f4[NN * 8];
__device__ float g_r4[NN * 8];
__device__ int   g_cnt[NN];
__device__ int   g_rowptr[NN + 1];
__device__ int   g_cur[NN];
__device__ int   g_csrc[EE];
__device__ int   g_bsum[64];

// ---------------- fp32 -> fp16 converts --------------------------------------
__global__ void k_cvt(const float4* __restrict__ in, uint2* __restrict__ out, int n4) {
    int i = blockIdx.x * blockDim.x + threadIdx.x;
    if (i >= n4) return;
    float4 v = in[i];
    uint2 o;
    o.x = h2_as_u32(__floats2half2_rn(v.x, v.y));
    o.y = h2_as_u32(__floats2half2_rn(v.z, v.w));
    out[i] = o;
}

__global__ void k_cvtW(const float4* __restrict__ w1, uint2* __restrict__ o1,
                       const float4* __restrict__ w2, uint2* __restrict__ o2,
                       const float4* __restrict__ w3, uint2* __restrict__ o3) {
    int i = blockIdx.x * blockDim.x + threadIdx.x;
    if (i < 8192) {
        float4 v = w1[i];
        o1[i] = make_uint2(h2_as_u32(__floats2half2_rn(v.x, v.y)),
                           h2_as_u32(__floats2half2_rn(v.z, v.w)));
    }
    if (i < 16384) {
        float4 v = w2[i];
        o2[i] = make_uint2(h2_as_u32(__floats2half2_rn(v.x, v.y)),
                           h2_as_u32(__floats2half2_rn(v.z, v.w)));
        float4 u = w3[i];
        o3[i] = make_uint2(h2_as_u32(__floats2half2_rn(u.x, u.y)),
                           h2_as_u32(__floats2half2_rn(u.z, u.w)));
    }
}

// ---------------- CSR build --------------------------------------------------
__global__ void k_zero_cnt(int* cnt) {
    int i = blockIdx.x * blockDim.x + threadIdx.x;
    if (i < NN) cnt[i] = 0;
}

__global__ void k_histo(const int* __restrict__ dst, int* __restrict__ cnt, int E) {
    for (int i = blockIdx.x * blockDim.x + threadIdx.x; i < E; i += gridDim.x * blockDim.x)
        atomicAdd(&cnt[dst[i]], 1);
}

__global__ void k_scan_part(const int* __restrict__ cnt) {
    __shared__ int sh[1024];
    int i = blockIdx.x * 1024 + threadIdx.x;
    sh[threadIdx.x] = (i < NN) ? cnt[i] : 0;
    __syncthreads();
    for (int o = 512; o > 0; o >>= 1) {
        if (threadIdx.x < o) sh[threadIdx.x] += sh[threadIdx.x + o];
        __syncthreads();
    }
    if (threadIdx.x == 0) g_bsum[blockIdx.x] = sh[0];
}

__global__ void k_scan_small(int* rowptr) {
    __shared__ int sh[64];
    int t = threadIdx.x;
    int v = (t < NB) ? g_bsum[t] : 0;
    sh[t] = v;
    __syncthreads();
    #pragma unroll
    for (int o = 1; o < 64; o <<= 1) {
        int u = (t >= o) ? sh[t - o] : 0;
        __syncthreads();
        sh[t] += u;
        __syncthreads();
    }
    if (t < NB) g_bsum[t] = sh[t] - v;       // exclusive prefix
    if (t == 63) rowptr[NN] = sh[63];
}

__global__ void k_scan_final(const int* __restrict__ cnt, int* __restrict__ rowptr,
                             int* __restrict__ cur) {
    __shared__ int sh[1024];
    int tid = threadIdx.x;
    int i = blockIdx.x * 1024 + tid;
    int v = (i < NN) ? cnt[i] : 0;
    sh[tid] = v;
    __syncthreads();
    #pragma unroll
    for (int o = 1; o < 1024; o <<= 1) {
        int t = (tid >= o) ? sh[tid - o] : 0;
        __syncthreads();
        sh[tid] += t;
        __syncthreads();
    }
    if (i < NN) { int ex = g_bsum[blockIdx.x] + sh[tid] - v; rowptr[i] = ex; cur[i] = ex; }
}

__global__ void k_scatter(const int* __restrict__ src, const int* __restrict__ dst,
                          int* __restrict__ cur, int* __restrict__ csrc, int E) {
    for (int i = blockIdx.x * blockDim.x + threadIdx.x; i < E; i += gridDim.x * blockDim.x) {
        int d = dst[i];
        int p = atomicAdd(&cur[d], 1);
        csrc[p] = src[i];
    }
}

// ---------------- fp16 GEMM (cp.async double-buffered) + fused el/er ---------
// C[M,256] = A[M,K] @ B[256,K]^T, fp16 in/out, fp32 accum.
// blockIdx.x = head (BN=64=HID). Epilogue emits el/er[n][head] in fp32.
#define BM 128
#define BN 64
#define BKB 64                    // fp16 k per stage
#define BKBP 72                   // +8 pad
#define ASZB (BM * BKBP)
#define BSZB (BN * BKBP)
#define GEMM_SMEM ((2 * (ASZB + BSZB)) * (int)sizeof(__half))

__device__ __forceinline__ void cp16(uint32_t s, const void* g) {
    asm volatile("cp.async.cg.shared.global [%0], [%1], 16;" :: "r"(s), "l"(g));
}

__device__ __forceinline__ void mma_fp16(float (&d)[4], const uint32_t (&a)[4],
                                         const uint32_t (&b)[2]) {
    asm volatile(
        "mma.sync.aligned.m16n8k16.row.col.f32.f16.f16.f32 "
        "{%0,%1,%2,%3},{%4,%5,%6,%7},{%8,%9},{%0,%1,%2,%3};"
        : "+f"(d[0]), "+f"(d[1]), "+f"(d[2]), "+f"(d[3])
        : "r"(a[0]), "r"(a[1]), "r"(a[2]), "r"(a[3]), "r"(b[0]), "r"(b[1]));
}

__global__ void __launch_bounds__(256) k_gemm_fp16(
        const __half* __restrict__ A, const __half* __restrict__ B,
        __half* __restrict__ C,
        const float* __restrict__ al, const float* __restrict__ ar,
        float* __restrict__ el, float* __restrict__ er, int M, int K) {
    extern __shared__ __half smem[];
    __half* Asm = smem;                 // [2][BM][BKBP]
    __half* Bsm = smem + 2 * ASZB;      // [2][BN][BKBP]
    __shared__ float sAl[BN], sAr[BN];
    __shared__ float sEl[2][BM], sEr[2][BM];

    const int head = blockIdx.x;
    const int bm = blockIdx.y * BM, bn = head * BN;
    const int tid = threadIdx.x;
    const int warp = tid >> 5, lane = tid & 31;
    const int wm = warp & 3, wn = warp >> 2;
    const int r = lane >> 2, c = lane & 3;

    if (tid < BN) { sAl[tid] = al[bn + tid]; sAr[tid] = ar[bn + tid]; }

    const int arow = tid >> 1, acol = (tid & 1) * 32;
    const int brow = tid >> 2, bcol = (tid & 3) * 16;
    const bool aok = (bm + arow) < M;

    float acc[2][4][4];
    #pragma unroll
    for (int mt = 0; mt < 2; mt++)
        #pragma unroll
        for (int nt = 0; nt < 4; nt++)
            #pragma unroll
            for (int i = 0; i < 4; i++) acc[mt][nt][i] = 0.f;

    const int ntile = K / BKB;

    auto issue = [&](int buf, int kt) {
        if (aok) {
            uint32_t sa = (uint32_t)__cvta_generic_to_shared(
                &Asm[(buf * BM + arow) * BKBP + acol]);
            const __half* ga = &A[(size_t)(bm + arow) * K + kt + acol];
            #pragma unroll
            for (int j = 0; j < 4; j++) cp16(sa + j * 16, ga + j * 8);
        }
        uint32_t sb = (uint32_t)__cvta_generic_to_shared(
            &Bsm[(buf * BN + brow) * BKBP + bcol]);
        const __half* gb = &B[(size_t)(bn + brow) * K + kt + bcol];
        #pragma unroll
        for (int j = 0; j < 2; j++) cp16(sb + j * 16, gb + j * 8);
    };

    issue(0, 0);
    asm volatile("cp.async.commit_group;");

    for (int t = 0; t < ntile; t++) {
        if (t + 1 < ntile) {
            issue((t + 1) & 1, (t + 1) * BKB);
            asm volatile("cp.async.commit_group;");
            asm volatile("cp.async.wait_group 1;");
        } else {
            asm volatile("cp.async.wait_group 0;");
        }
        __syncthreads();
        const __half* Ab = &Asm[((t & 1) * BM) * BKBP];
        const __half* Bb = &Bsm[((t & 1) * BN) * BKBP];
        #pragma unroll
        for (int kk = 0; kk < BKB; kk += 16) {
            uint32_t af[2][4], bf[4][2];
            #pragma unroll
            for (int mt = 0; mt < 2; mt++) {
                int row0 = wm * 32 + mt * 16 + r;
                af[mt][0] = *(const uint32_t*)&Ab[row0 * BKBP + kk + 2 * c];
                af[mt][1] = *(const uint32_t*)&Ab[(row0 + 8) * BKBP + kk + 2 * c];
                af[mt][2] = *(const uint32_t*)&Ab[row0 * BKBP + kk + 2 * c + 8];
                af[mt][3] = *(const uint32_t*)&Ab[(row0 + 8) * BKBP + kk + 2 * c + 8];
            }
            #pragma unroll
            for (int nt = 0; nt < 4; nt++) {
                int col0 = wn * 32 + nt * 8 + r;
                bf[nt][0] = *(const uint32_t*)&Bb[col0 * BKBP + kk + 2 * c];
                bf[nt][1] = *(const uint32_t*)&Bb[col0 * BKBP + kk + 2 * c + 8];
            }
            #pragma unroll
            for (int mt = 0; mt < 2; mt++)
                #pragma unroll
                for (int nt = 0; nt < 4; nt++)
                    mma_fp16(acc[mt][nt], af[mt], bf[nt]);
        }
        __syncthreads();
    }

    // ---- store fp16 feat ----
    #pragma unroll
    for (int mt = 0; mt < 2; mt++) {
        #pragma unroll
        for (int nt = 0; nt < 4; nt++) {
            int row = bm + wm * 32 + mt * 16 + r;
            int col = bn + wn * 32 + nt * 8 + 2 * c;
            if (row < M)
                *(__half2*)&C[(size_t)row * FD + col] =
                    __floats2half2_rn(acc[mt][nt][0], acc[mt][nt][1]);
            if (row + 8 < M)
                *(__half2*)&C[(size_t)(row + 8) * FD + col] =
                    __floats2half2_rn(acc[mt][nt][2], acc[mt][nt][3]);
        }
    }

    // ---- fused el/er: per-row dot with al/ar for this head (fp32 accs) ----
    #pragma unroll
    for (int mt = 0; mt < 2; mt++) {
        #pragma unroll
        for (int rh = 0; rh < 2; rh++) {
            float se = 0.f, sr2 = 0.f;
            #pragma unroll
            for (int nt = 0; nt < 4; nt++) {
                int col = wn * 32 + nt * 8 + 2 * c;
                float a0 = acc[mt][nt][rh * 2], a1 = acc[mt][nt][rh * 2 + 1];
                se  += a0 * sAl[col] + a1 * sAl[col + 1];
                sr2 += a0 * sAr[col] + a1 * sAr[col + 1];
            }
            se  += __shfl_xor_sync(0xffffffffu, se, 1);
            se  += __shfl_xor_sync(0xffffffffu, se, 2);
            sr2 += __shfl_xor_sync(0xffffffffu, sr2, 1);
            sr2 += __shfl_xor_sync(0xffffffffu, sr2, 2);
            if (c == 0) {
                int rowl = wm * 32 + mt * 16 + rh * 8 + r;
                sEl[wn][rowl] = se;
                sEr[wn][rowl] = sr2;
            }
        }
    }
    __syncthreads();
    if (tid < BM) {
        int row = bm + tid;
        if (row < M) {
            el[row * 4 + head] = sEl[0][tid] + sEl[1][tid];
            er[row * 4 + head] = sEr[0][tid] + sEr[1][tid];
        }
    }
}

// ---------------- fused edge aggregation: warp per node, fp16 gather ---------
// Writes fp32 h (residual path) and optional fp16 shadow (next GEMM input).
__global__ void __launch_bounds__(128) k_edge_agg(
        const uint4* __restrict__ feath,      // [N][32] x (8 fp16)
        const float4* __restrict__ el4, const float4* __restrict__ er4,
        const int* __restrict__ rowptr, const int* __restrict__ csrc,
        const float4* __restrict__ hprev4, const float4* __restrict__ bias4,
        float4* __restrict__ hout4, uint4* __restrict__ houth) {
    int w = threadIdx.x >> 5;
    int n = blockIdx.x * 4 + w;
    int lane = threadIdx.x & 31;
    if (n >= NN) return;
    int head = lane >> 3;
    __shared__ int   ssrc[4][32];
    __shared__ float sw[4][32][4];
    int beg = rowptr[n], end = rowptr[n + 1];
    float4 erd = er4[n];
    float acc[8];
    #pragma unroll
    for (int i = 0; i < 8; i++) acc[i] = 0.f;
    float4 dl = make_float4(0.f, 0.f, 0.f, 0.f);

    #define ACCUM(fv, wgt) do {                                             \
        const __half2* _p = (const __half2*)&(fv);                          \
        _Pragma("unroll")                                                   \
        for (int _j = 0; _j < 4; _j++) {                                    \
            float2 _v = __half22float2(_p[_j]);                             \
            acc[2 * _j]     = fmaf(_v.x, (wgt), acc[2 * _j]);               \
            acc[2 * _j + 1] = fmaf(_v.y, (wgt), acc[2 * _j + 1]);           \
        } } while (0)

    for (int base = beg; base < end; base += 32) {
        int cnt = min(32, end - base);
        if (lane < cnt) {
            int s = csrc[base + lane];
            ssrc[w][lane] = s;
            float4 le = el4[s];
            float x0 = le.x + erd.x; x0 = x0 > 0.f ? x0 : NEG * x0;
            float x1 = le.y + erd.y; x1 = x1 > 0.f ? x1 : NEG * x1;
            float x2 = le.z + erd.z; x2 = x2 > 0.f ? x2 : NEG * x2;
            float x3 = le.w + erd.w; x3 = x3 > 0.f ? x3 : NEG * x3;
            float w0 = expf(x0), w1 = expf(x1), w2 = expf(x2), w3 = expf(x3);
            sw[w][lane][0] = w0; sw[w][lane][1] = w1;
            sw[w][lane][2] = w2; sw[w][lane][3] = w3;
            dl.x += w0; dl.y += w1; dl.z += w2; dl.w += w3;
        }
        __syncwarp();
        int e = 0;
        for (; e + 4 <= cnt; e += 4) {
            uint4 f0 = feath[(size_t)ssrc[w][e]     * 32 + lane];
            uint4 f1 = feath[(size_t)ssrc[w][e + 1] * 32 + lane];
            uint4 f2 = feath[(size_t)ssrc[w][e + 2] * 32 + lane];
            uint4 f3 = feath[(size_t)ssrc[w][e + 3] * 32 + lane];
            float w0 = sw[w][e][head],     w1 = sw[w][e + 1][head];
            float w2 = sw[w][e + 2][head], w3 = sw[w][e + 3][head];
            ACCUM(f0, w0); ACCUM(f1, w1); ACCUM(f2, w2); ACCUM(f3, w3);
        }
        for (; e < cnt; e++) {
            uint4 fv = feath[(size_t)ssrc[w][e] * 32 + lane];
            float wg = sw[w][e][head];
            ACCUM(fv, wg);
        }
        __syncwarp();
    }
    #undef ACCUM

    #pragma unroll
    for (int o = 16; o > 0; o >>= 1) {
        dl.x += __shfl_xor_sync(0xffffffffu, dl.x, o);
        dl.y += __shfl_xor_sync(0xffffffffu, dl.y, o);
        dl.z += __shfl_xor_sync(0xffffffffu, dl.z, o);
        dl.w += __shfl_xor_sync(0xffffffffu, dl.w, o);
    }
    float den = (head == 0) ? dl.x : (head == 1) ? dl.y : (head == 2) ? dl.z : dl.w;
    float inv = (end > beg) ? 1.f / den : 0.f;
    float4 b0 = bias4[lane * 2], b1 = bias4[lane * 2 + 1];
    float4 v0 = make_float4(acc[0] * inv + b0.x, acc[1] * inv + b0.y,
                            acc[2] * inv + b0.z, acc[3] * inv + b0.w);
    float4 v1 = make_float4(acc[4] * inv + b1.x, acc[5] * inv + b1.y,
                            acc[6] * inv + b1.z, acc[7] * inv + b1.w);
    if (hprev4) {
        float4 p0 = hprev4[(size_t)n * 64 + lane * 2];
        float4 p1 = hprev4[(size_t)n * 64 + lane * 2 + 1];
        v0.x += p0.x; v0.y += p0.y; v0.z += p0.z; v0.w += p0.w;
        v1.x += p1.x; v1.y += p1.y; v1.z += p1.z; v1.w += p1.w;
    }
    v0.x = v0.x > 0.f ? v0.x : expm1f(v0.x);
    v0.y = v0.y > 0.f ? v0.y : expm1f(v0.y);
    v0.z = v0.z > 0.f ? v0.z : expm1f(v0.z);
    v0.w = v0.w > 0.f ? v0.w : expm1f(v0.w);
    v1.x = v1.x > 0.f ? v1.x : expm1f(v1.x);
    v1.y = v1.y > 0.f ? v1.y : expm1f(v1.y);
    v1.z = v1.z > 0.f ? v1.z : expm1f(v1.z);
    v1.w = v1.w > 0.f ? v1.w : expm1f(v1.w);
    hout4[(size_t)n * 64 + lane * 2]     = v0;
    hout4[(size_t)n * 64 + lane * 2 + 1] = v1;
    if (houth) {
        uint4 ob;
        ob.x = h2_as_u32(__floats2half2_rn(v0.x, v0.y));
        ob.y = h2_as_u32(__floats2half2_rn(v0.z, v0.w));
        ob.z = h2_as_u32(__floats2half2_rn(v1.x, v1.y));
        ob.w = h2_as_u32(__floats2half2_rn(v1.z, v1.w));
        houth[(size_t)n * 32 + lane] = ob;
    }
}

// ---------------- layer-4 projection + el/er (merged) ------------------------
__global__ void k_l4_proj(const float* __restrict__ h, const float* __restrict__ W4,
                          const float* __restrict__ rW4,
                          const float* __restrict__ al4, const float* __restrict__ ar4,
                          float* __restrict__ f4, float* __restrict__ r4,
                          float* __restrict__ el, float* __restrict__ er) {
    int n = blockIdx.x * 8 + (threadIdx.x >> 5);
    int lane = threadIdx.x & 31;
    if (n >= NN) return;
    float acc[16];
    #pragma unroll
    for (int o = 0; o < 16; o++) acc[o] = 0.f;
    const float* hr = h + (size_t)n * FD;
    for (int k = lane; k < FD; k += 32) {
        float hv = hr[k];
        #pragma unroll
        for (int o = 0; o < 8; o++) acc[o]     = fmaf(hv, W4[o * FD + k], acc[o]);
        #pragma unroll
        for (int o = 0; o < 8; o++) acc[8 + o] = fmaf(hv, rW4[o * FD + k], acc[8 + o]);
    }
    #pragma unroll
    for (int o = 0; o < 16; o++)
        #pragma unroll
        for (int off = 16; off > 0; off >>= 1)
            acc[o] += __shfl_xor_sync(0xffffffffu, acc[o], off);
    if (lane < 8) {
        f4[n * 8 + lane] = acc[lane];
        r4[n * 8 + lane] = acc[8 + lane];
    }
    if (lane < 4) {
        el[n * 4 + lane] = acc[2 * lane] * al4[2 * lane] +
                           acc[2 * lane + 1] * al4[2 * lane + 1];
        er[n * 4 + lane] = acc[2 * lane] * ar4[2 * lane] +
                           acc[2 * lane + 1] * ar4[2 * lane + 1];
    }
}

// ---------------- layer-4 edge agg + softmax + head-mean ---------------------
__global__ void k_l4_edge(const float* __restrict__ f4, const float* __restrict__ el,
                          const float* __restrict__ er, const int* __restrict__ rowptr,
                          const int* __restrict__ csrc, const float* __restrict__ r4,
                          const float* __restrict__ b4, float* __restrict__ out) {
    int n = blockIdx.x * 8 + (threadIdx.x >> 5);
    int lane = threadIdx.x & 31;
    if (n >= NN) return;
    int beg = rowptr[n], end = rowptr[n + 1];
    float4 erd = ((const float4*)er)[n];
    float acc[8] = {0, 0, 0, 0, 0, 0, 0, 0};
    float den[4] = {0, 0, 0, 0};
    for (int e = beg + lane; e < end; e += 32) {
        int s = csrc[e];
        float4 le = ((const float4*)el)[s];
        float x0 = le.x + erd.x; x0 = x0 > 0.f ? x0 : NEG * x0;
        float x1 = le.y + erd.y; x1 = x1 > 0.f ? x1 : NEG * x1;
        float x2 = le.z + erd.z; x2 = x2 > 0.f ? x2 : NEG * x2;
        float x3 = le.w + erd.w; x3 = x3 > 0.f ? x3 : NEG * x3;
        float w0 = expf(x0), w1 = expf(x1), w2 = expf(x2), w3 = expf(x3);
        den[0] += w0; den[1] += w1; den[2] += w2; den[3] += w3;
        float4 f0 = ((const float4*)f4)[s * 2];
        float4 f1 = ((const float4*)f4)[s * 2 + 1];
        acc[0] = fmaf(f0.x, w0, acc[0]);  acc[1] = fmaf(f0.y, w0, acc[1]);
        acc[2] = fmaf(f0.z, w1, acc[2]);  acc[3] = fmaf(f0.w, w1, acc[3]);
        acc[4] = fmaf(f1.x, w2, acc[4]);  acc[5] = fmaf(f1.y, w2, acc[5]);
        acc[6] = fmaf(f1.z, w3, acc[6]);  acc[7] = fmaf(f1.w, w3, acc[7]);
    }
    #pragma unroll
    for (int off = 16; off > 0; off >>= 1) {
        #pragma unroll
        for (int o = 0; o < 8; o++) acc[o] += __shfl_xor_sync(0xffffffffu, acc[o], off);
        #pragma unroll
        for (int h = 0; h < 4; h++) den[h] += __shfl_xor_sync(0xffffffffu, den[h], off);
    }
    if (lane == 0) {
        bool has = end > beg;
        float o0 = 0.f, o1 = 0.f;
        #pragma unroll
        for (int h = 0; h < 4; h++) {
            float r0 = has ? acc[2 * h] / den[h] : 0.f;
            float r1 = has ? acc[2 * h + 1] / den[h] : 0.f;
            r0 += r4[n * 8 + 2 * h] + b4[2 * h];
            r1 += r4[n * 8 + 2 * h + 1] + b4[2 * h + 1];
            float m = fmaxf(r0, r1);
            float e0 = expf(r0 - m), e1 = expf(r1 - m);
            float s = e0 + e1;
            o0 += e0 / s;
            o1 += e1 / s;
        }
        out[n * 2 + 0] = o0 * 0.25f;
        out[n * 2 + 1] = o1 * 0.25f;
    }
}

// ---------------- host launcher ----------------------------------------------
extern "C" void kernel_launch(void* const* d_in, const int* in_sizes, int n_in,
                              void* d_out, int out_size) {
    const float* x     = (const float*)d_in[0];
    const int*   src   = (const int*)  d_in[1];
    const int*   dst   = (const int*)  d_in[2];
    const float* W1    = (const float*)d_in[3];
    const float* al1   = (const float*)d_in[4];
    const float* ar1   = (const float*)d_in[5];
    const float* b1    = (const float*)d_in[6];
    const float* W2    = (const float*)d_in[7];
    const float* al2   = (const float*)d_in[8];
    const float* ar2   = (const float*)d_in[9];
    const float* b2    = (const float*)d_in[10];
    const float* W3    = (const float*)d_in[11];
    const float* al3   = (const float*)d_in[12];
    const float* ar3   = (const float*)d_in[13];
    const float* b3    = (const float*)d_in[14];
    const float* W4    = (const float*)d_in[15];
    const float* al4   = (const float*)d_in[16];
    const float* ar4   = (const float*)d_in[17];
    const float* b4    = (const float*)d_in[18];
    const float* resW4 = (const float*)d_in[19];
    float* out = (float*)d_out;
    const int E = in_sizes[1];

    __half *feath, *xh, *hinh, *W1h, *W2h, *W3h;
    float *hA, *hB, *el, *er, *f4, *r4;
    int *cnt, *rowptr, *cur, *csrc;
    cudaGetSymbolAddress((void**)&feath,  g_feath);
    cudaGetSymbolAddress((void**)&xh,     g_xh);
    cudaGetSymbolAddress((void**)&hinh,   g_hinh);
    cudaGetSymbolAddress((void**)&W1h,    g_W1h);
    cudaGetSymbolAddress((void**)&W2h,    g_W2h);
    cudaGetSymbolAddress((void**)&W3h,    g_W3h);
    cudaGetSymbolAddress((void**)&hA,     g_hA);
    cudaGetSymbolAddress((void**)&hB,     g_hB);
    cudaGetSymbolAddress((void**)&el,     g_el);
    cudaGetSymbolAddress((void**)&er,     g_er);
    cudaGetSymbolAddress((void**)&f4,     g_f4);
    cudaGetSymbolAddress((void**)&r4,     g_r4);
    cudaGetSymbolAddress((void**)&cnt,    g_cnt);
    cudaGetSymbolAddress((void**)&rowptr, g_rowptr);
    cudaGetSymbolAddress((void**)&cur,    g_cur);
    cudaGetSymbolAddress((void**)&csrc,   g_csrc);

    cudaFuncSetAttribute(k_gemm_fp16,
                         cudaFuncAttributeMaxDynamicSharedMemorySize, GEMM_SMEM);

    // ---- input converts (independent of CSR) ----
    const int xn4 = NN * 128 / 4;
    k_cvt<<<(xn4 + 255) / 256, 256>>>((const float4*)x, (uint2*)xh, xn4);
    k_cvtW<<<(16384 + 255) / 256, 256>>>((const float4*)W1, (uint2*)W1h,
                                         (const float4*)W2, (uint2*)W2h,
                                         (const float4*)W3, (uint2*)W3h);

    // ---- CSR by dst ----
    k_zero_cnt<<<(NN + 255) / 256, 256>>>(cnt);
    k_histo<<<1024, 256>>>(dst, cnt, E);
    k_scan_part<<<NB, 1024>>>(cnt);
    k_scan_small<<<1, 64>>>(rowptr);
    k_scan_final<<<NB, 1024>>>(cnt, rowptr, cur);
    k_scatter<<<1024, 256>>>(src, dst, cur, csrc, E);

    dim3 gemm_grid(FD / BN, (NN + BM - 1) / BM);
    const int agg_grid = (NN + 3) / 4;

    // ---- layer 1 ----
    k_gemm_fp16<<<gemm_grid, 256, GEMM_SMEM>>>(xh, W1h, feath, al1, ar1, el, er, NN, 128);
    k_edge_agg<<<agg_grid, 128>>>((const uint4*)feath, (const float4*)el,
                                  (const float4*)er, rowptr, csrc, nullptr,
                                  (const float4*)b1, (float4*)hA, (uint4*)hinh);

    // ---- layer 2 ----
    k_gemm_fp16<<<gemm_grid, 256, GEMM_SMEM>>>(hinh, W2h, feath, al2, ar2, el, er, NN, FD);
    k_edge_agg<<<agg_grid, 128>>>((const uint4*)feath, (const float4*)el,
                                  (const float4*)er, rowptr, csrc,
                                  (const float4*)hA, (const float4*)b2, (float4*)hB,
                                  (uint4*)hinh);

    // ---- layer 3 ----
    k_gemm_fp16<<<gemm_grid, 256, GEMM_SMEM>>>(hinh, W3h, feath, al3, ar3, el, er, NN, FD);
    k_edge_agg<<<agg_grid, 128>>>((const uint4*)feath, (const float4*)el,
                                  (const float4*)er, rowptr, csrc,
                                  (const float4*)hB, (const float4*)b3, (float4*)hA,
                                  (uint4*)nullptr);

    // ---- layer 4 ----
    k_l4_proj<<<(NN + 7) / 8, 256>>>(hA, W4, resW4, al4, ar4, f4, r4, el, er);
    k_l4_edge<<<(NN + 7) / 8, 256>>>(f4, el, er, rowptr, csrc, r4, b4, out);
}

// round 10
// speedup vs baseline: 1.2637x; 1.0514x over previous
#include <cuda_runtime.h>
#include <cuda_fp16.h>
#include <cstdint>
#include <cstring>

#define NN 50000
#define EE 800000
#define FD 256          // H*HID
#define NEG 0.2f
#define NB 49           // ceil(NN/1024)

__device__ __forceinline__ uint32_t h2_as_u32(__half2 v) {
    uint32_t u;
    memcpy(&u, &v, 4);
    return u;
}

// ---------------- scratch (device globals; no allocation allowed) ------------
__device__ __half g_feath[(size_t)NN * FD];   // fp16 post-GEMM features
__device__ __half g_xh[(size_t)NN * 128];     // fp16 input x
__device__ __half g_hAh[(size_t)NN * FD];     // fp16 h ping
__device__ __half g_hBh[(size_t)NN * FD];     // fp16 h pong
__device__ __half g_W1h[256 * 128];
__device__ __half g_W2h[256 * 256];
__device__ __half g_W3h[256 * 256];
__device__ float g_el[NN * 4];
__device__ float g_er[NN * 4];
__device__ float g_f4[NN * 8];
__device__ float g_r4[NN * 8];
__device__ int   g_cnt[NN];
__device__ int   g_rowptr[NN + 1];
__device__ int   g_cur[NN];
__device__ int   g_csrc[EE];
__device__ int   g_bsum[64];

// ---------------- fp32 -> fp16 converts --------------------------------------
__global__ void k_cvt(const float4* __restrict__ in, uint2* __restrict__ out, int n4) {
    int i = blockIdx.x * blockDim.x + threadIdx.x;
    if (i >= n4) return;
    float4 v = in[i];
    uint2 o;
    o.x = h2_as_u32(__floats2half2_rn(v.x, v.y));
    o.y = h2_as_u32(__floats2half2_rn(v.z, v.w));
    out[i] = o;
}

__global__ void k_cvtW(const float4* __restrict__ w1, uint2* __restrict__ o1,
                       const float4* __restrict__ w2, uint2* __restrict__ o2,
                       const float4* __restrict__ w3, uint2* __restrict__ o3) {
    int i = blockIdx.x * blockDim.x + threadIdx.x;
    if (i < 8192) {
        float4 v = w1[i];
        o1[i] = make_uint2(h2_as_u32(__floats2half2_rn(v.x, v.y)),
                           h2_as_u32(__floats2half2_rn(v.z, v.w)));
    }
    if (i < 16384) {
        float4 v = w2[i];
        o2[i] = make_uint2(h2_as_u32(__floats2half2_rn(v.x, v.y)),
                           h2_as_u32(__floats2half2_rn(v.z, v.w)));
        float4 u = w3[i];
        o3[i] = make_uint2(h2_as_u32(__floats2half2_rn(u.x, u.y)),
                           h2_as_u32(__floats2half2_rn(u.z, u.w)));
    }
}

// ---------------- CSR build --------------------------------------------------
__global__ void k_zero_cnt(int* cnt) {
    int i = blockIdx.x * blockDim.x + threadIdx.x;
    if (i < NN) cnt[i] = 0;
}

__global__ void k_histo(const int* __restrict__ dst, int* __restrict__ cnt, int E) {
    for (int i = blockIdx.x * blockDim.x + threadIdx.x; i < E; i += gridDim.x * blockDim.x)
        atomicAdd(&cnt[dst[i]], 1);
}

__global__ void k_scan_part(const int* __restrict__ cnt) {
    __shared__ int sh[1024];
    int i = blockIdx.x * 1024 + threadIdx.x;
    sh[threadIdx.x] = (i < NN) ? cnt[i] : 0;
    __syncthreads();
    for (int o = 512; o > 0; o >>= 1) {
        if (threadIdx.x < o) sh[threadIdx.x] += sh[threadIdx.x + o];
        __syncthreads();
    }
    if (threadIdx.x == 0) g_bsum[blockIdx.x] = sh[0];
}

__global__ void k_scan_small(int* rowptr) {
    __shared__ int sh[64];
    int t = threadIdx.x;
    int v = (t < NB) ? g_bsum[t] : 0;
    sh[t] = v;
    __syncthreads();
    #pragma unroll
    for (int o = 1; o < 64; o <<= 1) {
        int u = (t >= o) ? sh[t - o] : 0;
        __syncthreads();
        sh[t] += u;
        __syncthreads();
    }
    if (t < NB) g_bsum[t] = sh[t] - v;       // exclusive prefix
    if (t == 63) rowptr[NN] = sh[63];
}

__global__ void k_scan_final(const int* __restrict__ cnt, int* __restrict__ rowptr,
                             int* __restrict__ cur) {
    __shared__ int sh[1024];
    int tid = threadIdx.x;
    int i = blockIdx.x * 1024 + tid;
    int v = (i < NN) ? cnt[i] : 0;
    sh[tid] = v;
    __syncthreads();
    #pragma unroll
    for (int o = 1; o < 1024; o <<= 1) {
        int t = (tid >= o) ? sh[tid - o] : 0;
        __syncthreads();
        sh[tid] += t;
        __syncthreads();
    }
    if (i < NN) { int ex = g_bsum[blockIdx.x] + sh[tid] - v; rowptr[i] = ex; cur[i] = ex; }
}

__global__ void k_scatter(const int* __restrict__ src, const int* __restrict__ dst,
                          int* __restrict__ cur, int* __restrict__ csrc, int E) {
    for (int i = blockIdx.x * blockDim.x + threadIdx.x; i < E; i += gridDim.x * blockDim.x) {
        int d = dst[i];
        int p = atomicAdd(&cur[d], 1);
        csrc[p] = src[i];
    }
}

// ---------------- fp16 GEMM BN=128 (cp.async dbuf) + fused el/er -------------
// C[M,256] = A[M,K] @ B[256,K]^T, fp16 in/out, fp32 accum.
// blockIdx.x covers 128 cols = 2 heads; warp wn (0/1) owns head bx*2+wn.
#define BM 128
#define BN 128
#define BKB 64                    // fp16 k per stage
#define BKBP 72                   // +8 pad
#define ASZB (BM * BKBP)
#define BSZB (BN * BKBP)
#define GEMM_SMEM ((2 * (ASZB + BSZB)) * (int)sizeof(__half))   // 73728 B

__device__ __forceinline__ void cp16(uint32_t s, const void* g) {
    asm volatile("cp.async.cg.shared.global [%0], [%1], 16;" :: "r"(s), "l"(g));
}

__device__ __forceinline__ void mma_fp16(float (&d)[4], const uint32_t (&a)[4],
                                         const uint32_t (&b)[2]) {
    asm volatile(
        "mma.sync.aligned.m16n8k16.row.col.f32.f16.f16.f32 "
        "{%0,%1,%2,%3},{%4,%5,%6,%7},{%8,%9},{%0,%1,%2,%3};"
        : "+f"(d[0]), "+f"(d[1]), "+f"(d[2]), "+f"(d[3])
        : "r"(a[0]), "r"(a[1]), "r"(a[2]), "r"(a[3]), "r"(b[0]), "r"(b[1]));
}

__global__ void __launch_bounds__(256) k_gemm_fp16(
        const __half* __restrict__ A, const __half* __restrict__ B,
        __half* __restrict__ C,
        const float* __restrict__ al, const float* __restrict__ ar,
        float* __restrict__ el, float* __restrict__ er, int M, int K) {
    extern __shared__ __half smem[];
    __half* Asm = smem;                 // [2][BM][BKBP]
    __half* Bsm = smem + 2 * ASZB;      // [2][BN][BKBP]
    __shared__ float sAl[BN], sAr[BN];

    const int bx = blockIdx.x;
    const int bm = blockIdx.y * BM, bn = bx * BN;
    const int tid = threadIdx.x;
    const int warp = tid >> 5, lane = tid & 31;
    const int wm = warp & 3, wn = warp >> 2;      // wn in {0,1}: head within block
    const int r = lane >> 2, c = lane & 3;
    const int hg = bx * 2 + wn;

    if (tid < BN) { sAl[tid] = al[bn + tid]; sAr[tid] = ar[bn + tid]; }

    // loaders: row = tid>>1 (0..127), 32 halfs per thread (4x cp16); same for B
    const int lrow = tid >> 1, lcol = (tid & 1) * 32;
    const bool aok = (bm + lrow) < M;

    float acc[2][8][4];
    #pragma unroll
    for (int mt = 0; mt < 2; mt++)
        #pragma unroll
        for (int nt = 0; nt < 8; nt++)
            #pragma unroll
            for (int i = 0; i < 4; i++) acc[mt][nt][i] = 0.f;

    const int ntile = K / BKB;

    auto issue = [&](int buf, int kt) {
        if (aok) {
            uint32_t sa = (uint32_t)__cvta_generic_to_shared(
                &Asm[(buf * BM + lrow) * BKBP + lcol]);
            const __half* ga = &A[(size_t)(bm + lrow) * K + kt + lcol];
            #pragma unroll
            for (int j = 0; j < 4; j++) cp16(sa + j * 16, ga + j * 8);
        }
        uint32_t sb = (uint32_t)__cvta_generic_to_shared(
            &Bsm[(buf * BN + lrow) * BKBP + lcol]);
        const __half* gb = &B[(size_t)(bn + lrow) * K + kt + lcol];
        #pragma unroll
        for (int j = 0; j < 4; j++) cp16(sb + j * 16, gb + j * 8);
    };

    issue(0, 0);
    asm volatile("cp.async.commit_group;");

    for (int t = 0; t < ntile; t++) {
        if (t + 1 < ntile) {
            issue((t + 1) & 1, (t + 1) * BKB);
            asm volatile("cp.async.commit_group;");
            asm volatile("cp.async.wait_group 1;");
        } else {
            asm volatile("cp.async.wait_group 0;");
        }
        __syncthreads();
        const __half* Ab = &Asm[((t & 1) * BM) * BKBP];
        const __half* Bb = &Bsm[((t & 1) * BN) * BKBP];
        #pragma unroll
        for (int kk = 0; kk < BKB; kk += 16) {
            uint32_t af[2][4], bf[8][2];
            #pragma unroll
            for (int mt = 0; mt < 2; mt++) {
                int row0 = wm * 32 + mt * 16 + r;
                af[mt][0] = *(const uint32_t*)&Ab[row0 * BKBP + kk + 2 * c];
                af[mt][1] = *(const uint32_t*)&Ab[(row0 + 8) * BKBP + kk + 2 * c];
                af[mt][2] = *(const uint32_t*)&Ab[row0 * BKBP + kk + 2 * c + 8];
                af[mt][3] = *(const uint32_t*)&Ab[(row0 + 8) * BKBP + kk + 2 * c + 8];
            }
            #pragma unroll
            for (int nt = 0; nt < 8; nt++) {
                int col0 = wn * 64 + nt * 8 + r;
                bf[nt][0] = *(const uint32_t*)&Bb[col0 * BKBP + kk + 2 * c];
                bf[nt][1] = *(const uint32_t*)&Bb[col0 * BKBP + kk + 2 * c + 8];
            }
            #pragma unroll
            for (int mt = 0; mt < 2; mt++)
                #pragma unroll
                for (int nt = 0; nt < 8; nt++)
                    mma_fp16(acc[mt][nt], af[mt], bf[nt]);
        }
        __syncthreads();
    }

    // ---- store fp16 feat ----
    #pragma unroll
    for (int mt = 0; mt < 2; mt++) {
        #pragma unroll
        for (int nt = 0; nt < 8; nt++) {
            int row = bm + wm * 32 + mt * 16 + r;
            int col = bn + wn * 64 + nt * 8 + 2 * c;
            if (row < M)
                *(__half2*)&C[(size_t)row * FD + col] =
                    __floats2half2_rn(acc[mt][nt][0], acc[mt][nt][1]);
            if (row + 8 < M)
                *(__half2*)&C[(size_t)(row + 8) * FD + col] =
                    __floats2half2_rn(acc[mt][nt][2], acc[mt][nt][3]);
        }
    }

    // ---- fused el/er: warp owns (rows wm*32..+31, head hg); direct write ----
    #pragma unroll
    for (int mt = 0; mt < 2; mt++) {
        #pragma unroll
        for (int rh = 0; rh < 2; rh++) {
            float se = 0.f, sr2 = 0.f;
            #pragma unroll
            for (int nt = 0; nt < 8; nt++) {
                int col = wn * 64 + nt * 8 + 2 * c;
                float a0 = acc[mt][nt][rh * 2], a1 = acc[mt][nt][rh * 2 + 1];
                se  += a0 * sAl[col] + a1 * sAl[col + 1];
                sr2 += a0 * sAr[col] + a1 * sAr[col + 1];
            }
            se  += __shfl_xor_sync(0xffffffffu, se, 1);
            se  += __shfl_xor_sync(0xffffffffu, se, 2);
            sr2 += __shfl_xor_sync(0xffffffffu, sr2, 1);
            sr2 += __shfl_xor_sync(0xffffffffu, sr2, 2);
            if (c == 0) {
                int row = bm + wm * 32 + mt * 16 + rh * 8 + r;
                if (row < M) {
                    el[row * 4 + hg] = se;
                    er[row * 4 + hg] = sr2;
                }
            }
        }
    }
}

// ---------------- fused edge aggregation: warp per node, fp16 everywhere -----
__global__ void __launch_bounds__(128) k_edge_agg(
        const uint4* __restrict__ feath,      // [N][32] x (8 fp16)
        const float4* __restrict__ el4, const float4* __restrict__ er4,
        const int* __restrict__ rowptr, const int* __restrict__ csrc,
        const uint4* __restrict__ hprevh,     // fp16 prev h or null
        const float4* __restrict__ bias4,
        uint4* __restrict__ houth) {          // fp16 out h
    int w = threadIdx.x >> 5;
    int n = blockIdx.x * 4 + w;
    int lane = threadIdx.x & 31;
    if (n >= NN) return;
    int head = lane >> 3;
    __shared__ int   ssrc[4][32];
    __shared__ float sw[4][32][4];
    int beg = rowptr[n], end = rowptr[n + 1];
    float4 erd = er4[n];
    float acc[8];
    #pragma unroll
    for (int i = 0; i < 8; i++) acc[i] = 0.f;
    float4 dl = make_float4(0.f, 0.f, 0.f, 0.f);

    #define ACCUM(fv, wgt) do {                                             \
        const __half2* _p = (const __half2*)&(fv);                          \
        _Pragma("unroll")                                                   \
        for (int _j = 0; _j < 4; _j++) {                                    \
            float2 _v = __half22float2(_p[_j]);                             \
            acc[2 * _j]     = fmaf(_v.x, (wgt), acc[2 * _j]);               \
            acc[2 * _j + 1] = fmaf(_v.y, (wgt), acc[2 * _j + 1]);           \
        } } while (0)

    for (int base = beg; base < end; base += 32) {
        int cnt = min(32, end - base);
        if (lane < cnt) {
            int s = csrc[base + lane];
            ssrc[w][lane] = s;
            float4 le = el4[s];
            float x0 = le.x + erd.x; x0 = x0 > 0.f ? x0 : NEG * x0;
            float x1 = le.y + erd.y; x1 = x1 > 0.f ? x1 : NEG * x1;
            float x2 = le.z + erd.z; x2 = x2 > 0.f ? x2 : NEG * x2;
            float x3 = le.w + erd.w; x3 = x3 > 0.f ? x3 : NEG * x3;
            float w0 = expf(x0), w1 = expf(x1), w2 = expf(x2), w3 = expf(x3);
            sw[w][lane][0] = w0; sw[w][lane][1] = w1;
            sw[w][lane][2] = w2; sw[w][lane][3] = w3;
            dl.x += w0; dl.y += w1; dl.z += w2; dl.w += w3;
        }
        __syncwarp();
        int e = 0;
        for (; e + 4 <= cnt; e += 4) {
            uint4 f0 = feath[(size_t)ssrc[w][e]     * 32 + lane];
            uint4 f1 = feath[(size_t)ssrc[w][e + 1] * 32 + lane];
            uint4 f2 = feath[(size_t)ssrc[w][e + 2] * 32 + lane];
            uint4 f3 = feath[(size_t)ssrc[w][e + 3] * 32 + lane];
            float w0 = sw[w][e][head],     w1 = sw[w][e + 1][head];
            float w2 = sw[w][e + 2][head], w3 = sw[w][e + 3][head];
            ACCUM(f0, w0); ACCUM(f1, w1); ACCUM(f2, w2); ACCUM(f3, w3);
        }
        for (; e < cnt; e++) {
            uint4 fv = feath[(size_t)ssrc[w][e] * 32 + lane];
            float wg = sw[w][e][head];
            ACCUM(fv, wg);
        }
        __syncwarp();
    }
    #undef ACCUM

    #pragma unroll
    for (int o = 16; o > 0; o >>= 1) {
        dl.x += __shfl_xor_sync(0xffffffffu, dl.x, o);
        dl.y += __shfl_xor_sync(0xffffffffu, dl.y, o);
        dl.z += __shfl_xor_sync(0xffffffffu, dl.z, o);
        dl.w += __shfl_xor_sync(0xffffffffu, dl.w, o);
    }
    float den = (head == 0) ? dl.x : (head == 1) ? dl.y : (head == 2) ? dl.z : dl.w;
    float inv = (end > beg) ? 1.f / den : 0.f;
    float4 b0 = bias4[lane * 2], b1 = bias4[lane * 2 + 1];
    float v[8];
    v[0] = acc[0] * inv + b0.x; v[1] = acc[1] * inv + b0.y;
    v[2] = acc[2] * inv + b0.z; v[3] = acc[3] * inv + b0.w;
    v[4] = acc[4] * inv + b1.x; v[5] = acc[5] * inv + b1.y;
    v[6] = acc[6] * inv + b1.z; v[7] = acc[7] * inv + b1.w;
    if (hprevh) {
        uint4 pv = hprevh[(size_t)n * 32 + lane];
        const __half2* pp = (const __half2*)&pv;
        #pragma unroll
        for (int j = 0; j < 4; j++) {
            float2 p = __half22float2(pp[j]);
            v[2 * j]     += p.x;
            v[2 * j + 1] += p.y;
        }
    }
    #pragma unroll
    for (int j = 0; j < 8; j++)
        v[j] = v[j] > 0.f ? v[j] : expm1f(v[j]);
    uint4 ob;
    ob.x = h2_as_u32(__floats2half2_rn(v[0], v[1]));
    ob.y = h2_as_u32(__floats2half2_rn(v[2], v[3]));
    ob.z = h2_as_u32(__floats2half2_rn(v[4], v[5]));
    ob.w = h2_as_u32(__floats2half2_rn(v[6], v[7]));
    houth[(size_t)n * 32 + lane] = ob;
}

// ---------------- layer-4 projection + el/er (merged, fp16 h) ----------------
__global__ void k_l4_proj(const __half* __restrict__ h, const float* __restrict__ W4,
                          const float* __restrict__ rW4,
                          const float* __restrict__ al4, const float* __restrict__ ar4,
                          float* __restrict__ f4, float* __restrict__ r4,
                          float* __restrict__ el, float* __restrict__ er) {
    int n = blockIdx.x * 8 + (threadIdx.x >> 5);
    int lane = threadIdx.x & 31;
    if (n >= NN) return;
    float acc[16];
    #pragma unroll
    for (int o = 0; o < 16; o++) acc[o] = 0.f;
    const __half* hr = h + (size_t)n * FD;
    #pragma unroll
    for (int k8 = 0; k8 < 8; k8++) {
        int k = k8 * 32 + lane;
        float hv = __half2float(hr[k]);
        #pragma unroll
        for (int o = 0; o < 8; o++) acc[o]     = fmaf(hv, W4[o * FD + k], acc[o]);
        #pragma unroll
        for (int o = 0; o < 8; o++) acc[8 + o] = fmaf(hv, rW4[o * FD + k], acc[8 + o]);
    }
    #pragma unroll
    for (int o = 0; o < 16; o++)
        #pragma unroll
        for (int off = 16; off > 0; off >>= 1)
            acc[o] += __shfl_xor_sync(0xffffffffu, acc[o], off);
    if (lane < 8) {
        f4[n * 8 + lane] = acc[lane];
        r4[n * 8 + lane] = acc[8 + lane];
    }
    if (lane < 4) {
        el[n * 4 + lane] = acc[2 * lane] * al4[2 * lane] +
                           acc[2 * lane + 1] * al4[2 * lane + 1];
        er[n * 4 + lane] = acc[2 * lane] * ar4[2 * lane] +
                           acc[2 * lane + 1] * ar4[2 * lane + 1];
    }
}

// ---------------- layer-4 edge agg + softmax + head-mean ---------------------
__global__ void k_l4_edge(const float* __restrict__ f4, const float* __restrict__ el,
                          const float* __restrict__ er, const int* __restrict__ rowptr,
                          const int* __restrict__ csrc, const float* __restrict__ r4,
                          const float* __restrict__ b4, float* __restrict__ out) {
    int n = blockIdx.x * 8 + (threadIdx.x >> 5);
    int lane = threadIdx.x & 31;
    if (n >= NN) return;
    int beg = rowptr[n], end = rowptr[n + 1];
    float4 erd = ((const float4*)er)[n];
    float acc[8] = {0, 0, 0, 0, 0, 0, 0, 0};
    float den[4] = {0, 0, 0, 0};
    for (int e = beg + lane; e < end; e += 32) {
        int s = csrc[e];
        float4 le = ((const float4*)el)[s];
        float x0 = le.x + erd.x; x0 = x0 > 0.f ? x0 : NEG * x0;
        float x1 = le.y + erd.y; x1 = x1 > 0.f ? x1 : NEG * x1;
        float x2 = le.z + erd.z; x2 = x2 > 0.f ? x2 : NEG * x2;
        float x3 = le.w + erd.w; x3 = x3 > 0.f ? x3 : NEG * x3;
        float w0 = expf(x0), w1 = expf(x1), w2 = expf(x2), w3 = expf(x3);
        den[0] += w0; den[1] += w1; den[2] += w2; den[3] += w3;
        float4 f0 = ((const float4*)f4)[s * 2];
        float4 f1 = ((const float4*)f4)[s * 2 + 1];
        acc[0] = fmaf(f0.x, w0, acc[0]);  acc[1] = fmaf(f0.y, w0, acc[1]);
        acc[2] = fmaf(f0.z, w1, acc[2]);  acc[3] = fmaf(f0.w, w1, acc[3]);
        acc[4] = fmaf(f1.x, w2, acc[4]);  acc[5] = fmaf(f1.y, w2, acc[5]);
        acc[6] = fmaf(f1.z, w3, acc[6]);  acc[7] = fmaf(f1.w, w3, acc[7]);
    }
    #pragma unroll
    for (int off = 16; off > 0; off >>= 1) {
        #pragma unroll
        for (int o = 0; o < 8; o++) acc[o] += __shfl_xor_sync(0xffffffffu, acc[o], off);
        #pragma unroll
        for (int h = 0; h < 4; h++) den[h] += __shfl_xor_sync(0xffffffffu, den[h], off);
    }
    if (lane == 0) {
        bool has = end > beg;
        float o0 = 0.f, o1 = 0.f;
        #pragma unroll
        for (int h = 0; h < 4; h++) {
            float r0 = has ? acc[2 * h] / den[h] : 0.f;
            float r1 = has ? acc[2 * h + 1] / den[h] : 0.f;
            r0 += r4[n * 8 + 2 * h] + b4[2 * h];
            r1 += r4[n * 8 + 2 * h + 1] + b4[2 * h + 1];
            float m = fmaxf(r0, r1);
            float e0 = expf(r0 - m), e1 = expf(r1 - m);
            float s = e0 + e1;
            o0 += e0 / s;
            o1 += e1 / s;
        }
        out[n * 2 + 0] = o0 * 0.25f;
        out[n * 2 + 1] = o1 * 0.25f;
    }
}

// ---------------- host launcher ----------------------------------------------
extern "C" void kernel_launch(void* const* d_in, const int* in_sizes, int n_in,
                              void* d_out, int out_size) {
    const float* x     = (const float*)d_in[0];
    const int*   src   = (const int*)  d_in[1];
    const int*   dst   = (const int*)  d_in[2];
    const float* W1    = (const float*)d_in[3];
    const float* al1   = (const float*)d_in[4];
    const float* ar1   = (const float*)d_in[5];
    const float* b1    = (const float*)d_in[6];
    const float* W2    = (const float*)d_in[7];
    const float* al2   = (const float*)d_in[8];
    const float* ar2   = (const float*)d_in[9];
    const float* b2    = (const float*)d_in[10];
    const float* W3    = (const float*)d_in[11];
    const float* al3   = (const float*)d_in[12];
    const float* ar3   = (const float*)d_in[13];
    const float* b3    = (const float*)d_in[14];
    const float* W4    = (const float*)d_in[15];
    const float* al4   = (const float*)d_in[16];
    const float* ar4   = (const float*)d_in[17];
    const float* b4    = (const float*)d_in[18];
    const float* resW4 = (const float*)d_in[19];
    float* out = (float*)d_out;
    const int E = in_sizes[1];

    __half *feath, *xh, *hAh, *hBh, *W1h, *W2h, *W3h;
    float *el, *er, *f4, *r4;
    int *cnt, *rowptr, *cur, *csrc;
    cudaGetSymbolAddress((void**)&feath,  g_feath);
    cudaGetSymbolAddress((void**)&xh,     g_xh);
    cudaGetSymbolAddress((void**)&hAh,    g_hAh);
    cudaGetSymbolAddress((void**)&hBh,    g_hBh);
    cudaGetSymbolAddress((void**)&W1h,    g_W1h);
    cudaGetSymbolAddress((void**)&W2h,    g_W2h);
    cudaGetSymbolAddress((void**)&W3h,    g_W3h);
    cudaGetSymbolAddress((void**)&el,     g_el);
    cudaGetSymbolAddress((void**)&er,     g_er);
    cudaGetSymbolAddress((void**)&f4,     g_f4);
    cudaGetSymbolAddress((void**)&r4,     g_r4);
    cudaGetSymbolAddress((void**)&cnt,    g_cnt);
    cudaGetSymbolAddress((void**)&rowptr, g_rowptr);
    cudaGetSymbolAddress((void**)&cur,    g_cur);
    cudaGetSymbolAddress((void**)&csrc,   g_csrc);

    cudaFuncSetAttribute(k_gemm_fp16,
                         cudaFuncAttributeMaxDynamicSharedMemorySize, GEMM_SMEM);

    // ---- input converts (independent of CSR) ----
    const int xn4 = NN * 128 / 4;
    k_cvt<<<(xn4 + 255) / 256, 256>>>((const float4*)x, (uint2*)xh, xn4);
    k_cvtW<<<(16384 + 255) / 256, 256>>>((const float4*)W1, (uint2*)W1h,
                                         (const float4*)W2, (uint2*)W2h,
                                         (const float4*)W3, (uint2*)W3h);

    // ---- CSR by dst ----
    k_zero_cnt<<<(NN + 255) / 256, 256>>>(cnt);
    k_histo<<<1024, 256>>>(dst, cnt, E);
    k_scan_part<<<NB, 1024>>>(cnt);
    k_scan_small<<<1, 64>>>(rowptr);
    k_scan_final<<<NB, 1024>>>(cnt, rowptr, cur);
    k_scatter<<<1024, 256>>>(src, dst, cur, csrc, E);

    dim3 gemm_grid(FD / BN, (NN + BM - 1) / BM);   // (2, 391)
    const int agg_grid = (NN + 3) / 4;

    // ---- layer 1 ----
    k_gemm_fp16<<<gemm_grid, 256, GEMM_SMEM>>>(xh, W1h, feath, al1, ar1, el, er, NN, 128);
    k_edge_agg<<<agg_grid, 128>>>((const uint4*)feath, (const float4*)el,
                                  (const float4*)er, rowptr, csrc, nullptr,
                                  (const float4*)b1, (uint4*)hAh);

    // ---- layer 2 ----
    k_gemm_fp16<<<gemm_grid, 256, GEMM_SMEM>>>(hAh, W2h, feath, al2, ar2, el, er, NN, FD);
    k_edge_agg<<<agg_grid, 128>>>((const uint4*)feath, (const float4*)el,
                                  (const float4*)er, rowptr, csrc,
                                  (const uint4*)hAh, (const float4*)b2, (uint4*)hBh);

    // ---- layer 3 ----
    k_gemm_fp16<<<gemm_grid, 256, GEMM_SMEM>>>(hBh, W3h, feath, al3, ar3, el, er, NN, FD);
    k_edge_agg<<<agg_grid, 128>>>((const uint4*)feath, (const float4*)el,
                                  (const float4*)er, rowptr, csrc,
                                  (const uint4*)hBh, (const float4*)b3, (uint4*)hAh);

    // ---- layer 4 ----
    k_l4_proj<<<(NN + 7) / 8, 256>>>(hAh, W4, resW4, al4, ar4, f4, r4, el, er);
    k_l4_edge<<<(NN + 7) / 8, 256>>>(f4, el, er, rowptr, csrc, r4, b4, out);
}